// round 10
// baseline (speedup 1.0000x reference)
#include <cuda_runtime.h>
#include <cuda_fp16.h>
#include <cstdint>

#define HHC 4096
#define OOC 4096
#define RRC 64
#define PIT 72   // smem pitch in halves (144 B)

// smem (bytes):
//   Xbuf[b] = b*4608          [0, 9216)
//   Abuf[b] = 9216 + b*9216   [9216, 27648)
//   phase2: per-warp B slots  w*2304, [0, 18432)   (overlaps X/A, after phase1)
//   Ts      = 27648           [27648, 32256)
#define SMEM_TOTAL 32256

// pre-converted fp16 weights (4 MB each)
__device__ __half g_ah[(size_t)8 * RRC * HHC];
__device__ __half g_bh[(size_t)8 * OOC * RRC];

__device__ __forceinline__ void hmma16816(float* c,
                                          uint32_t a0, uint32_t a1, uint32_t a2, uint32_t a3,
                                          uint32_t b0, uint32_t b1) {
    asm volatile(
        "mma.sync.aligned.m16n8k16.row.col.f32.f16.f16.f32 "
        "{%0,%1,%2,%3}, {%4,%5,%6,%7}, {%8,%9}, {%0,%1,%2,%3};"
        : "+f"(c[0]), "+f"(c[1]), "+f"(c[2]), "+f"(c[3])
        : "r"(a0), "r"(a1), "r"(a2), "r"(a3), "r"(b0), "r"(b1));
}

__device__ __forceinline__ uint32_t h2u(__half2 h) {
    return *reinterpret_cast<uint32_t*>(&h);
}

__device__ __forceinline__ void cp16(uint32_t dst, const void* src) {
    asm volatile("cp.async.cg.shared.global [%0], [%1], 16;"
                 :: "r"(dst), "l"(src) : "memory");
}
#define CP_COMMIT() asm volatile("cp.async.commit_group;" ::: "memory")
#define CP_WAIT0()  asm volatile("cp.async.wait_group 0;" ::: "memory")

// ---------------- prep: convert lora_a / lora_b to fp16 ----------------
__global__ __launch_bounds__(256) void lora_prep(const float* __restrict__ la,
                                                 const float* __restrict__ lb) {
    const size_t NA = (size_t)8 * RRC * HHC / 4;   // 524288 float4 per tensor
    size_t i = (size_t)blockIdx.x * 256 + threadIdx.x;
    const float4* src; uint2* dh; size_t j;
    if (i < NA) { src = (const float4*)la; dh = (uint2*)g_ah; j = i; }
    else        { src = (const float4*)lb; dh = (uint2*)g_bh; j = i - NA; }
    float4 a = src[j];
    __half2 h0 = __floats2half2_rn(a.x, a.y);
    __half2 h1 = __floats2half2_rn(a.z, a.w);
    dh[j] = make_uint2(h2u(h0), h2u(h1));
}

// ---------------- fused LoRA ----------------
__global__ __launch_bounds__(256, 4) void lora_fused(
    const float* __restrict__ result,
    const float* __restrict__ data,
    const float* __restrict__ mask,
    const float* __restrict__ scalings,
    float* __restrict__ out)
{
    extern __shared__ char smem[];
    const uint32_t sbase = (uint32_t)__cvta_generic_to_shared(smem);

    const int t    = threadIdx.x;
    const int w    = t >> 5;
    const int lane = t & 31;
    const int g    = lane >> 2;
    const int t4   = lane & 3;

    const int wm = w & 1;          // phase1 M slab (16 rows of 32)
    const int wn = w >> 1;         // phase1 N slice (16 cols of 64)

    const int m0 = blockIdx.x * 32;
    const int n  = blockIdx.x >> 6;       // 64 CTAs per adapter
    const float sc = __ldg(scalings + n);

    const int row0 = wm * 16 + g;

    // ======================== PHASE 1 (unchanged from R8) ========================
    float accT[2][4] = {};

    const float* dbase = data + (size_t)m0 * HHC;
    const float* mbase = mask + (size_t)m0 * HHC;
    const __half* ahb = g_ah + (size_t)n * RRC * HHC;

    const int xr = t >> 4, xq = t & 15;
    const int ar = t >> 3, aq = t & 7;

    #pragma unroll
    for (int i = 0; i < 2; i++) {
        int row = ar + i * 32;
        cp16(sbase + 9216u + (uint32_t)row * 144u + aq * 16u,
             ahb + (size_t)row * HHC + aq * 8);
    }
    CP_COMMIT();

    float4 dreg[2], mreg[2];
    #pragma unroll
    for (int i = 0; i < 2; i++) {
        int row = xr + i * 16;
        dreg[i] = __ldcs((const float4*)(dbase + (size_t)row * HHC) + xq);
        mreg[i] = __ldcs((const float4*)(mbase + (size_t)row * HHC) + xq);
    }

    for (int ch = 0; ch < 64; ch++) {
        const int b = ch & 1;
        __half* Xs = (__half*)(smem + b * 4608);
        const __half* Ah = (const __half*)(smem + 9216 + b * 9216);

        #pragma unroll
        for (int i = 0; i < 2; i++) {
            int row = xr + i * 16;
            float4 d4 = dreg[i], m4 = mreg[i];
            __half2 h0 = __floats2half2_rn(d4.x * m4.x * sc, d4.y * m4.y * sc);
            __half2 h1 = __floats2half2_rn(d4.z * m4.z * sc, d4.w * m4.w * sc);
            *(uint2*)(Xs + row * PIT + xq * 4) = make_uint2(h2u(h0), h2u(h1));
        }
        CP_WAIT0();
        __syncthreads();

        if (ch + 1 < 64) {
            const int ho = (ch + 1) * 64;
            #pragma unroll
            for (int i = 0; i < 2; i++) {
                int row = ar + i * 32;
                cp16(sbase + 9216u + (uint32_t)(b ^ 1) * 9216u + (uint32_t)row * 144u + aq * 16u,
                     ahb + (size_t)row * HHC + ho + aq * 8);
            }
            CP_COMMIT();
            #pragma unroll
            for (int i = 0; i < 2; i++) {
                int row = xr + i * 16;
                dreg[i] = __ldcs((const float4*)(dbase + (size_t)row * HHC + ho) + xq);
                mreg[i] = __ldcs((const float4*)(mbase + (size_t)row * HHC + ho) + xq);
            }
        }

        #pragma unroll
        for (int s = 0; s < 4; s++) {
            const int kb = s * 16 + t4 * 2;
            uint32_t a0 = *(const uint32_t*)(Xs + row0 * PIT + kb);
            uint32_t a1 = *(const uint32_t*)(Xs + (row0 + 8) * PIT + kb);
            uint32_t a2 = *(const uint32_t*)(Xs + row0 * PIT + kb + 8);
            uint32_t a3 = *(const uint32_t*)(Xs + (row0 + 8) * PIT + kb + 8);
            #pragma unroll
            for (int j = 0; j < 2; j++) {
                const int nr = wn * 16 + j * 8 + g;
                uint32_t b0 = *(const uint32_t*)(Ah + nr * PIT + kb);
                uint32_t b1 = *(const uint32_t*)(Ah + nr * PIT + kb + 8);
                hmma16816(accT[j], a0, a1, a2, a3, b0, b1);
            }
        }
    }

    // ---- quantize T into smem ----
    __half* Ts = (__half*)(smem + 27648);
    #pragma unroll
    for (int j = 0; j < 2; j++) {
        const int c = wn * 16 + j * 8 + t4 * 2;
        __half2 h0 = __floats2half2_rn(accT[j][0], accT[j][1]);
        __half2 h1 = __floats2half2_rn(accT[j][2], accT[j][3]);
        *(uint32_t*)(Ts + row0 * PIT + c)       = h2u(h0);
        *(uint32_t*)(Ts + (row0 + 8) * PIT + c) = h2u(h1);
    }
    __syncthreads();   // Ts published; all phase1 smem reads done

    // ======================== PHASE 2: warp-autonomous, no CTA syncs ========================
    // COVERAGE FIX: 8 warps = 2 m-slabs x 4 o-ranges (1024 cols each).
    const int ws = w & 1;          // m slab for phase 2
    const int wo = w >> 1;         // o-range 0..3
    const int prow0 = ws * 16 + g; // this warp's phase-2 row

    // ---- hoist T fragments for this slab (loop-invariant over o) ----
    uint32_t ta[4][4];
    #pragma unroll
    for (int s = 0; s < 4; s++) {
        const int kb = s * 16 + t4 * 2;
        ta[s][0] = *(const uint32_t*)(Ts + prow0 * PIT + kb);
        ta[s][1] = *(const uint32_t*)(Ts + (prow0 + 8) * PIT + kb);
        ta[s][2] = *(const uint32_t*)(Ts + prow0 * PIT + kb + 8);
        ta[s][3] = *(const uint32_t*)(Ts + (prow0 + 8) * PIT + kb + 8);
    }

    const __half* bhb = g_bh + (size_t)n * OOC * RRC;
    __half* slot = (__half*)(smem + w * 2304);
    const int owarp = wo * 1024;

    // B tile loader mapping: chunk c = lane + 32*i; row = c>>3, 16B-offset = c&7
    const int brow0 = lane >> 3;
    const int boff  = lane & 7;

    uint4 breg[4];
    #pragma unroll
    for (int i = 0; i < 4; i++) {
        int row = brow0 + i * 4;
        breg[i] = *(const uint4*)(bhb + (size_t)(owarp + row) * RRC + boff * 8);
    }

    for (int it = 0; it < 64; it++) {
        const int obase = owarp + it * 16;

        __syncwarp();   // prior iteration's LDS complete before overwrite
        #pragma unroll
        for (int i = 0; i < 4; i++) {
            int row = brow0 + i * 4;
            *(uint4*)(slot + row * PIT + boff * 8) = breg[i];
        }
        __syncwarp();

        // prefetch next B tile (overlaps compute)
        if (it + 1 < 64) {
            const int onext = owarp + (it + 1) * 16;
            #pragma unroll
            for (int i = 0; i < 4; i++) {
                int row = brow0 + i * 4;
                breg[i] = *(const uint4*)(bhb + (size_t)(onext + row) * RRC + boff * 8);
            }
        }

        // ---- MMA ----
        float acc[2][4] = {};
        #pragma unroll
        for (int s = 0; s < 4; s++) {
            const int kb = s * 16 + t4 * 2;
            #pragma unroll
            for (int j = 0; j < 2; j++) {
                const int nr = j * 8 + g;
                uint32_t b0 = *(const uint32_t*)(slot + nr * PIT + kb);
                uint32_t b1 = *(const uint32_t*)(slot + nr * PIT + kb + 8);
                hmma16816(acc[j], ta[s][0], ta[s][1], ta[s][2], ta[s][3], b0, b1);
            }
        }

        // ---- epilogue: residual add + store ----
        #pragma unroll
        for (int j = 0; j < 2; j++) {
            const int ocol = obase + j * 8 + t4 * 2;
            size_t gi0 = (size_t)(m0 + prow0) * OOC + ocol;
            size_t gi1 = (size_t)(m0 + prow0 + 8) * OOC + ocol;
            float2 r0 = __ldcs((const float2*)(result + gi0));
            float2 r1 = __ldcs((const float2*)(result + gi1));
            __stcs((float2*)(out + gi0), make_float2(r0.x + acc[j][0], r0.y + acc[j][1]));
            __stcs((float2*)(out + gi1), make_float2(r1.x + acc[j][2], r1.y + acc[j][3]));
        }
    }
}

extern "C" void kernel_launch(void* const* d_in, const int* in_sizes, int n_in,
                              void* d_out, int out_size) {
    const float* result   = (const float*)d_in[0];
    const float* data     = (const float*)d_in[1];
    const float* mask     = (const float*)d_in[2];
    const float* lora_a   = (const float*)d_in[3];
    const float* lora_b   = (const float*)d_in[4];
    const float* scalings = (const float*)d_in[5];
    float* out = (float*)d_out;

    lora_prep<<<4096, 256>>>(lora_a, lora_b);

    cudaFuncSetAttribute(lora_fused, cudaFuncAttributeMaxDynamicSharedMemorySize, SMEM_TOTAL);
    lora_fused<<<512, 256, SMEM_TOTAL>>>(result, data, mask, scalings, out);
}

// round 11
// speedup vs baseline: 1.1184x; 1.1184x over previous
#include <cuda_runtime.h>
#include <cuda_fp16.h>
#include <cstdint>

#define HHC 4096
#define OOC 4096
#define RRC 64
#define PIT 72   // smem pitch in halves (144 B)

// smem (bytes):
//   Xbuf[b] = b*4608          [0, 9216)
//   Abuf[b] = 9216 + b*9216   [9216, 27648)
//   Bbuf[b] = b*9216          [0, 18432)   (phase2, overlaps X/A after final sync)
//   Ts      = 27648           [27648, 32256)
#define SMEM_TOTAL 32256

// pre-converted fp16 weights (4 MB each)
__device__ __half g_ah[(size_t)8 * RRC * HHC];
__device__ __half g_bh[(size_t)8 * OOC * RRC];

__device__ __forceinline__ void hmma16816(float* c,
                                          uint32_t a0, uint32_t a1, uint32_t a2, uint32_t a3,
                                          uint32_t b0, uint32_t b1) {
    asm volatile(
        "mma.sync.aligned.m16n8k16.row.col.f32.f16.f16.f32 "
        "{%0,%1,%2,%3}, {%4,%5,%6,%7}, {%8,%9}, {%0,%1,%2,%3};"
        : "+f"(c[0]), "+f"(c[1]), "+f"(c[2]), "+f"(c[3])
        : "r"(a0), "r"(a1), "r"(a2), "r"(a3), "r"(b0), "r"(b1));
}

__device__ __forceinline__ uint32_t h2u(__half2 h) {
    return *reinterpret_cast<uint32_t*>(&h);
}

__device__ __forceinline__ void cp16(uint32_t dst, const void* src) {
    asm volatile("cp.async.cg.shared.global [%0], [%1], 16;"
                 :: "r"(dst), "l"(src) : "memory");
}
#define CP_COMMIT() asm volatile("cp.async.commit_group;" ::: "memory")
#define CP_WAIT0()  asm volatile("cp.async.wait_group 0;" ::: "memory")

// ---------------- prep: convert lora_a / lora_b to fp16 ----------------
__global__ __launch_bounds__(256) void lora_prep(const float* __restrict__ la,
                                                 const float* __restrict__ lb) {
    const size_t NA = (size_t)8 * RRC * HHC / 4;   // 524288 float4 per tensor
    size_t i = (size_t)blockIdx.x * 256 + threadIdx.x;
    const float4* src; uint2* dh; size_t j;
    if (i < NA) { src = (const float4*)la; dh = (uint2*)g_ah; j = i; }
    else        { src = (const float4*)lb; dh = (uint2*)g_bh; j = i - NA; }
    float4 a = src[j];
    __half2 h0 = __floats2half2_rn(a.x, a.y);
    __half2 h1 = __floats2half2_rn(a.z, a.w);
    dh[j] = make_uint2(h2u(h0), h2u(h1));
}

// ---------------- fused LoRA ----------------
__global__ __launch_bounds__(256, 4) void lora_fused(
    const float* __restrict__ result,
    const float* __restrict__ data,
    const float* __restrict__ mask,
    const float* __restrict__ scalings,
    float* __restrict__ out)
{
    extern __shared__ char smem[];
    const uint32_t sbase = (uint32_t)__cvta_generic_to_shared(smem);

    const int t    = threadIdx.x;
    const int w    = t >> 5;
    const int lane = t & 31;
    const int g    = lane >> 2;
    const int t4   = lane & 3;

    const int wm = w & 1;          // M slab (16 rows of 32)
    const int wn = w >> 1;         // N slice (16 cols of 64)

    const int m0 = blockIdx.x * 32;
    const int n  = blockIdx.x >> 6;       // 64 CTAs per adapter
    const float sc = __ldg(scalings + n);

    const int row0 = wm * 16 + g;

    // ======================== PHASE 1 (identical to R8) ========================
    float accT[2][4] = {};

    const float* dbase = data + (size_t)m0 * HHC;
    const float* mbase = mask + (size_t)m0 * HHC;
    const __half* ahb = g_ah + (size_t)n * RRC * HHC;

    const int xr = t >> 4, xq = t & 15;
    const int ar = t >> 3, aq = t & 7;

    #pragma unroll
    for (int i = 0; i < 2; i++) {
        int row = ar + i * 32;
        cp16(sbase + 9216u + (uint32_t)row * 144u + aq * 16u,
             ahb + (size_t)row * HHC + aq * 8);
    }
    CP_COMMIT();

    float4 dreg[2], mreg[2];
    #pragma unroll
    for (int i = 0; i < 2; i++) {
        int row = xr + i * 16;
        dreg[i] = __ldcs((const float4*)(dbase + (size_t)row * HHC) + xq);
        mreg[i] = __ldcs((const float4*)(mbase + (size_t)row * HHC) + xq);
    }

    for (int ch = 0; ch < 64; ch++) {
        const int b = ch & 1;
        __half* Xs = (__half*)(smem + b * 4608);
        const __half* Ah = (const __half*)(smem + 9216 + b * 9216);

        #pragma unroll
        for (int i = 0; i < 2; i++) {
            int row = xr + i * 16;
            float4 d4 = dreg[i], m4 = mreg[i];
            __half2 h0 = __floats2half2_rn(d4.x * m4.x * sc, d4.y * m4.y * sc);
            __half2 h1 = __floats2half2_rn(d4.z * m4.z * sc, d4.w * m4.w * sc);
            *(uint2*)(Xs + row * PIT + xq * 4) = make_uint2(h2u(h0), h2u(h1));
        }
        CP_WAIT0();
        __syncthreads();

        if (ch + 1 < 64) {
            const int ho = (ch + 1) * 64;
            #pragma unroll
            for (int i = 0; i < 2; i++) {
                int row = ar + i * 32;
                cp16(sbase + 9216u + (uint32_t)(b ^ 1) * 9216u + (uint32_t)row * 144u + aq * 16u,
                     ahb + (size_t)row * HHC + ho + aq * 8);
            }
            CP_COMMIT();
            #pragma unroll
            for (int i = 0; i < 2; i++) {
                int row = xr + i * 16;
                dreg[i] = __ldcs((const float4*)(dbase + (size_t)row * HHC + ho) + xq);
                mreg[i] = __ldcs((const float4*)(mbase + (size_t)row * HHC + ho) + xq);
            }
        }

        #pragma unroll
        for (int s = 0; s < 4; s++) {
            const int kb = s * 16 + t4 * 2;
            uint32_t a0 = *(const uint32_t*)(Xs + row0 * PIT + kb);
            uint32_t a1 = *(const uint32_t*)(Xs + (row0 + 8) * PIT + kb);
            uint32_t a2 = *(const uint32_t*)(Xs + row0 * PIT + kb + 8);
            uint32_t a3 = *(const uint32_t*)(Xs + (row0 + 8) * PIT + kb + 8);
            #pragma unroll
            for (int j = 0; j < 2; j++) {
                const int nr = wn * 16 + j * 8 + g;
                uint32_t b0 = *(const uint32_t*)(Ah + nr * PIT + kb);
                uint32_t b1 = *(const uint32_t*)(Ah + nr * PIT + kb + 8);
                hmma16816(accT[j], a0, a1, a2, a3, b0, b1);
            }
        }
    }

    // ---- quantize T into smem ----
    __half* Ts = (__half*)(smem + 27648);
    #pragma unroll
    for (int j = 0; j < 2; j++) {
        const int c = wn * 16 + j * 8 + t4 * 2;
        __half2 h0 = __floats2half2_rn(accT[j][0], accT[j][1]);
        __half2 h1 = __floats2half2_rn(accT[j][2], accT[j][3]);
        *(uint32_t*)(Ts + row0 * PIT + c)       = h2u(h0);
        *(uint32_t*)(Ts + (row0 + 8) * PIT + c) = h2u(h1);
    }
    __syncthreads();   // Ts published; all phase1 smem reads done

    // ======================== PHASE 2: R8 structure + T-frag hoist + result pipeline ==========
    // ---- hoist T fragments (loop-invariant over o) ----
    uint32_t ta[4][4];
    #pragma unroll
    for (int s = 0; s < 4; s++) {
        const int kb = s * 16 + t4 * 2;
        ta[s][0] = *(const uint32_t*)(Ts + row0 * PIT + kb);
        ta[s][1] = *(const uint32_t*)(Ts + (row0 + 8) * PIT + kb);
        ta[s][2] = *(const uint32_t*)(Ts + row0 * PIT + kb + 8);
        ta[s][3] = *(const uint32_t*)(Ts + (row0 + 8) * PIT + kb + 8);
    }

    const __half* bhb = g_bh + (size_t)n * OOC * RRC;
    const int br = t >> 3, bq = t & 7;

    // preamble: cp.async B oc 0 -> buf 0
    #pragma unroll
    for (int i = 0; i < 2; i++) {
        int row = br + i * 32;
        cp16(sbase + (uint32_t)row * 144u + bq * 16u,
             bhb + (size_t)row * RRC + bq * 8);
    }
    CP_COMMIT();

    // preamble: residual loads for oc = 0
    float2 rcur[2][2];
    #pragma unroll
    for (int j = 0; j < 2; j++) {
        const int ocol = wn * 16 + j * 8 + t4 * 2;
        rcur[j][0] = __ldcs((const float2*)(result + (size_t)(m0 + row0) * OOC + ocol));
        rcur[j][1] = __ldcs((const float2*)(result + (size_t)(m0 + row0 + 8) * OOC + ocol));
    }

    for (int oc = 0; oc < 64; oc++) {
        const int b = oc & 1;
        const __half* Bh = (const __half*)(smem + b * 9216);
        const int o0 = oc * 64;

        CP_WAIT0();
        __syncthreads();

        // issue next B tile
        if (oc + 1 < 64) {
            const int on = (oc + 1) * 64;
            #pragma unroll
            for (int i = 0; i < 2; i++) {
                int row = br + i * 32;
                cp16(sbase + (uint32_t)(b ^ 1) * 9216u + (uint32_t)row * 144u + bq * 16u,
                     bhb + (size_t)(on + row) * RRC + bq * 8);
            }
            CP_COMMIT();
        }

        // prefetch residual for next iteration (latency covered by MMA + epilogue)
        float2 rnxt[2][2];
        if (oc + 1 < 64) {
            const int onb = o0 + 64;
            #pragma unroll
            for (int j = 0; j < 2; j++) {
                const int ocol = onb + wn * 16 + j * 8 + t4 * 2;
                rnxt[j][0] = __ldcs((const float2*)(result + (size_t)(m0 + row0) * OOC + ocol));
                rnxt[j][1] = __ldcs((const float2*)(result + (size_t)(m0 + row0 + 8) * OOC + ocol));
            }
        }

        // ---- MMA: K = 64 = 4 k16 steps ----
        float acc[2][4] = {};
        #pragma unroll
        for (int s = 0; s < 4; s++) {
            const int kb = s * 16 + t4 * 2;
            #pragma unroll
            for (int j = 0; j < 2; j++) {
                const int nr = wn * 16 + j * 8 + g;
                uint32_t b0 = *(const uint32_t*)(Bh + nr * PIT + kb);
                uint32_t b1 = *(const uint32_t*)(Bh + nr * PIT + kb + 8);
                hmma16816(acc[j], ta[s][0], ta[s][1], ta[s][2], ta[s][3], b0, b1);
            }
        }

        // ---- epilogue: residual (preloaded) add + store ----
        #pragma unroll
        for (int j = 0; j < 2; j++) {
            const int ocol = o0 + wn * 16 + j * 8 + t4 * 2;
            size_t gi0 = (size_t)(m0 + row0) * OOC + ocol;
            size_t gi1 = (size_t)(m0 + row0 + 8) * OOC + ocol;
            __stcs((float2*)(out + gi0),
                   make_float2(rcur[j][0].x + acc[j][0], rcur[j][0].y + acc[j][1]));
            __stcs((float2*)(out + gi1),
                   make_float2(rcur[j][1].x + acc[j][2], rcur[j][1].y + acc[j][3]));
        }
        #pragma unroll
        for (int j = 0; j < 2; j++) {
            rcur[j][0] = rnxt[j][0];
            rcur[j][1] = rnxt[j][1];
        }
    }
}

extern "C" void kernel_launch(void* const* d_in, const int* in_sizes, int n_in,
                              void* d_out, int out_size) {
    const float* result   = (const float*)d_in[0];
    const float* data     = (const float*)d_in[1];
    const float* mask     = (const float*)d_in[2];
    const float* lora_a   = (const float*)d_in[3];
    const float* lora_b   = (const float*)d_in[4];
    const float* scalings = (const float*)d_in[5];
    float* out = (float*)d_out;

    lora_prep<<<4096, 256>>>(lora_a, lora_b);

    cudaFuncSetAttribute(lora_fused, cudaFuncAttributeMaxDynamicSharedMemorySize, SMEM_TOTAL);
    lora_fused<<<512, 256, SMEM_TOTAL>>>(result, data, mask, scalings, out);
}